// round 1
// baseline (speedup 1.0000x reference)
#include <cuda_runtime.h>
#include <math.h>

// RMSPELoss: per-row 4x4 circular-distance assignment min over 24 perms,
// mean over batch. HBM-bound label scan (94.9 MB).

#define BATCH 131072
#define NC 181
#define DD 4
#define PI_F 3.14159265358979323846f
#define TWOPI_F 6.283185307179586f

__device__ double g_acc; // zero-initialized at module load; re-zeroed by finalize each call

__constant__ unsigned char c_perms[24][4] = {
    {0,1,2,3},{0,1,3,2},{0,2,1,3},{0,2,3,1},{0,3,1,2},{0,3,2,1},
    {1,0,2,3},{1,0,3,2},{1,2,0,3},{1,2,3,0},{1,3,0,2},{1,3,2,0},
    {2,0,1,3},{2,0,3,1},{2,1,0,3},{2,1,3,0},{2,3,0,1},{2,3,1,0},
    {3,0,1,2},{3,0,2,1},{3,1,0,2},{3,1,2,0},{3,2,0,1},{3,2,1,0}
};

__device__ __forceinline__ float sq_mod_diff(float a, float b) {
    // jnp.mod(a - b + pi, 2pi) - pi, then squared. jnp.mod returns [0, 2pi).
    float x = a - b + PI_F;
    float m = fmodf(x, TWOPI_F);
    if (m < 0.0f) m += TWOPI_F;
    float d = m - PI_F;
    return d * d;
}

// 1024 threads = 32 warps per block, one warp per row.
__global__ __launch_bounds__(1024, 1)
void rmspe_main(const float* __restrict__ logits, const int* __restrict__ labels) {
    const int lane   = threadIdx.x & 31;
    const int warpId = threadIdx.x >> 5;
    const int row    = blockIdx.x * 32 + warpId;   // grid = BATCH/32 blocks

    __shared__ int   s_idx[32][4];
    __shared__ float s_part[32];

    const long base = (long)row * NC;

    // ---- coalesced label scan: 6 x 32 lanes covers 181 (+ guard) ----
    int v[6];
    #pragma unroll
    for (int i = 0; i < 6; i++) {
        int c = i * 32 + lane;
        v[i] = (c < NC) ? labels[base + c] : 0;
    }

    // ---- collect the 4 one-positions (order irrelevant: min over all perms) ----
    int cnt = 0;
    #pragma unroll
    for (int i = 0; i < 6; i++) {
        bool f = (v[i] == 1);
        unsigned m = __ballot_sync(0xffffffffu, f);
        if (f) {
            int pos = cnt + __popc(m & ((1u << lane) - 1u));
            if (pos < 4) s_idx[warpId][pos] = i * 32 + lane;
        }
        cnt += __popc(m);
    }
    __syncwarp();

    float rmse = 0.0f;
    if (lane == 0) {
        float doa[4], ang[4];
        #pragma unroll
        for (int k = 0; k < 4; k++) doa[k] = logits[base + k];
        #pragma unroll
        for (int j = 0; j < 4; j++)
            ang[j] = ((float)s_idx[warpId][j] - 90.0f) * (PI_F / 180.0f);

        float cost[4][4];
        #pragma unroll
        for (int i = 0; i < 4; i++)
            #pragma unroll
            for (int j = 0; j < 4; j++)
                cost[i][j] = sq_mod_diff(doa[i], ang[j]);

        float best = 3.402823466e+38f;
        #pragma unroll
        for (int p = 0; p < 24; p++) {
            float t = cost[0][c_perms[p][0]] + cost[1][c_perms[p][1]]
                    + cost[2][c_perms[p][2]] + cost[3][c_perms[p][3]];
            best = fminf(best, t);
        }
        rmse = sqrtf(best * 0.25f);
        s_part[warpId] = rmse;
    }
    __syncthreads();

    // ---- block reduction: warp 0 sums the 32 partials, one double atomic per block ----
    if (warpId == 0) {
        float x = s_part[lane];
        #pragma unroll
        for (int off = 16; off > 0; off >>= 1)
            x += __shfl_down_sync(0xffffffffu, x, off);
        if (lane == 0)
            atomicAdd(&g_acc, (double)x);
    }
}

__global__ void rmspe_finalize(float* __restrict__ out) {
    out[0] = (float)(g_acc / (double)BATCH);
    g_acc = 0.0;  // deterministic state for next graph replay
}

extern "C" void kernel_launch(void* const* d_in, const int* in_sizes, int n_in,
                              void* d_out, int out_size) {
    const float* logits = (const float*)d_in[0];
    const int*   labels = (const int*)d_in[1];
    float* out = (float*)d_out;

    rmspe_main<<<BATCH / 32, 1024>>>(logits, labels);
    rmspe_finalize<<<1, 1>>>(out);
}

// round 2
// speedup vs baseline: 3.5622x; 3.5622x over previous
#include <cuda_runtime.h>
#include <math.h>

// RMSPELoss: per-row 4x4 circular-distance assignment min over 24 perms, mean
// over batch. R2: smem-staged int4 label loads (single latency wave, logits
// loaded concurrently), lane-parallel cost/perm evaluation, occ=2.

#define BATCH 131072
#define NC 181
#define ROWS_PER_BLOCK 32
#define INTS_PER_BLOCK (NC * ROWS_PER_BLOCK)   // 5792 ints = 23168 B (16B-aligned per block)
#define INT4_PER_BLOCK (INTS_PER_BLOCK / 4)    // 1448
#define PI_F 3.14159265358979323846f
#define TWOPI_F 6.283185307179586f
#define INV_TWOPI_F 0.15915494309189535f

__device__ double g_acc;  // zeroed at load; re-zeroed by finalize each call

#define PK(a,b,c,d) ((unsigned)(a) | ((unsigned)(b)<<8) | ((unsigned)(c)<<16) | ((unsigned)(d)<<24))
__constant__ unsigned c_perm_packed[24] = {
    PK(0,1,2,3),PK(0,1,3,2),PK(0,2,1,3),PK(0,2,3,1),PK(0,3,1,2),PK(0,3,2,1),
    PK(1,0,2,3),PK(1,0,3,2),PK(1,2,0,3),PK(1,2,3,0),PK(1,3,0,2),PK(1,3,2,0),
    PK(2,0,1,3),PK(2,0,3,1),PK(2,1,0,3),PK(2,1,3,0),PK(2,3,0,1),PK(2,3,1,0),
    PK(3,0,1,2),PK(3,0,2,1),PK(3,1,0,2),PK(3,1,2,0),PK(3,2,0,1),PK(3,2,1,0)
};

__global__ __launch_bounds__(1024, 2)
void rmspe_main(const float* __restrict__ logits, const int* __restrict__ labels) {
    __shared__ __align__(16) int s_lab[INTS_PER_BLOCK];
    __shared__ float    s_doa[ROWS_PER_BLOCK][4];
    __shared__ float    s_cost[ROWS_PER_BLOCK][16];
    __shared__ int      s_idx[ROWS_PER_BLOCK][4];
    __shared__ float    s_part[ROWS_PER_BLOCK];
    __shared__ unsigned s_perm[24];

    const int tid  = threadIdx.x;
    const int lane = tid & 31;
    const int w    = tid >> 5;                       // warp = row within block
    const long row0 = (long)blockIdx.x * ROWS_PER_BLOCK;

    // ---- phase 1: ONE latency wave. int4-coalesced label staging + logits ----
    const int4* g4 = reinterpret_cast<const int4*>(labels + row0 * NC);
    int4* s4 = reinterpret_cast<int4*>(s_lab);
    #pragma unroll
    for (int i = tid; i < INT4_PER_BLOCK; i += 1024) s4[i] = g4[i];

    if (tid < ROWS_PER_BLOCK * 4) {
        int r = tid >> 2, k = tid & 3;
        s_doa[r][k] = logits[(row0 + r) * NC + k];
    }
    if (tid < 24) s_perm[tid] = c_perm_packed[tid];
    __syncthreads();

    // ---- phase 2: find the 4 one-positions of row w (order irrelevant) ----
    int cnt = 0;
    #pragma unroll
    for (int i = 0; i < 6; i++) {
        int c = i * 32 + lane;
        int v = (c < NC) ? s_lab[w * NC + c] : 0;
        bool f = (v == 1);
        unsigned m = __ballot_sync(0xffffffffu, f);
        if (f) {
            int pos = cnt + __popc(m & ((1u << lane) - 1u));
            if (pos < 4) s_idx[w][pos] = c;
        }
        cnt += __popc(m);
    }
    __syncwarp();

    // ---- phase 3: 16 lanes compute the 4x4 cost matrix in parallel ----
    if (lane < 16) {
        int i = lane >> 2, j = lane & 3;
        float a = s_doa[w][i];
        float b = ((float)s_idx[w][j] - 90.0f) * (PI_F / 180.0f);
        float x = a - b + PI_F;
        float m = x - TWOPI_F * floorf(x * INV_TWOPI_F);  // mod(x, 2pi) in [0,2pi)
        float d = m - PI_F;
        s_cost[w][lane] = d * d;
    }
    __syncwarp();

    // ---- phase 4: 24 lanes each evaluate one permutation; warp-min ----
    float t = 3.402823466e+38f;
    if (lane < 24) {
        unsigned p = s_perm[lane];
        t = s_cost[w][      (p        & 0xffu)]
          + s_cost[w][ 4 + ((p >>  8) & 0xffu)]
          + s_cost[w][ 8 + ((p >> 16) & 0xffu)]
          + s_cost[w][12 + ( p >> 24        )];
    }
    #pragma unroll
    for (int off = 16; off; off >>= 1)
        t = fminf(t, __shfl_xor_sync(0xffffffffu, t, off));
    if (lane == 0) s_part[w] = sqrtf(t * 0.25f);
    __syncthreads();

    // ---- phase 5: block reduce, one double RED per block ----
    if (w == 0) {
        float x = s_part[lane];
        #pragma unroll
        for (int off = 16; off; off >>= 1)
            x += __shfl_down_sync(0xffffffffu, x, off);
        if (lane == 0) atomicAdd(&g_acc, (double)x);
    }
}

__global__ void rmspe_finalize(float* __restrict__ out) {
    out[0] = (float)(g_acc / (double)BATCH);
    g_acc = 0.0;  // deterministic across graph replays
}

extern "C" void kernel_launch(void* const* d_in, const int* in_sizes, int n_in,
                              void* d_out, int out_size) {
    const float* logits = (const float*)d_in[0];
    const int*   labels = (const int*)d_in[1];
    float* out = (float*)d_out;

    rmspe_main<<<BATCH / ROWS_PER_BLOCK, 1024>>>(logits, labels);
    rmspe_finalize<<<1, 1>>>(out);
}

// round 3
// speedup vs baseline: 3.5646x; 1.0007x over previous
#include <cuda_runtime.h>
#include <math.h>

// RMSPELoss R3: fused single-kernel (last-block epilogue), 256-thread blocks
// (8 rows/block, 8 blocks/SM) for fine-grained load/compute overlap.

#define BATCH 131072
#define NC 181
#define ROWS_PER_BLOCK 8
#define THREADS 256
#define NBLOCKS (BATCH / ROWS_PER_BLOCK)               // 16384
#define INTS_PER_BLOCK (NC * ROWS_PER_BLOCK)           // 1448 ints = 5792 B (16B-aligned)
#define INT4_PER_BLOCK (INTS_PER_BLOCK / 4)            // 362
#define PI_F 3.14159265358979323846f
#define TWOPI_F 6.283185307179586f
#define INV_TWOPI_F 0.15915494309189535f

__device__ double   g_acc;   // zeroed at load; reset by last block each call
__device__ unsigned g_done;  // completion counter, ditto

#define PK(a,b,c,d) ((unsigned)(a) | ((unsigned)(b)<<8) | ((unsigned)(c)<<16) | ((unsigned)(d)<<24))
__constant__ unsigned c_perm_packed[24] = {
    PK(0,1,2,3),PK(0,1,3,2),PK(0,2,1,3),PK(0,2,3,1),PK(0,3,1,2),PK(0,3,2,1),
    PK(1,0,2,3),PK(1,0,3,2),PK(1,2,0,3),PK(1,2,3,0),PK(1,3,0,2),PK(1,3,2,0),
    PK(2,0,1,3),PK(2,0,3,1),PK(2,1,0,3),PK(2,1,3,0),PK(2,3,0,1),PK(2,3,1,0),
    PK(3,0,1,2),PK(3,0,2,1),PK(3,1,0,2),PK(3,1,2,0),PK(3,2,0,1),PK(3,2,1,0)
};

__global__ __launch_bounds__(THREADS, 8)
void rmspe_main(const float* __restrict__ logits, const int* __restrict__ labels,
                float* __restrict__ out) {
    __shared__ __align__(16) int s_lab[INTS_PER_BLOCK];
    __shared__ float    s_doa[ROWS_PER_BLOCK][4];
    __shared__ float    s_cost[ROWS_PER_BLOCK][16];
    __shared__ int      s_idx[ROWS_PER_BLOCK][4];
    __shared__ float    s_part[ROWS_PER_BLOCK];
    __shared__ unsigned s_perm[24];

    const int tid  = threadIdx.x;
    const int lane = tid & 31;
    const int w    = tid >> 5;                       // warp = row within block
    const long row0 = (long)blockIdx.x * ROWS_PER_BLOCK;

    // ---- phase 1: one latency wave — int4 label staging + logits + perms ----
    const int4* g4 = reinterpret_cast<const int4*>(labels + row0 * NC);
    int4* s4 = reinterpret_cast<int4*>(s_lab);
    #pragma unroll
    for (int i = tid; i < INT4_PER_BLOCK; i += THREADS) s4[i] = g4[i];

    if (tid < ROWS_PER_BLOCK * 4) {
        int r = tid >> 2, k = tid & 3;
        s_doa[r][k] = logits[(row0 + r) * NC + k];
    }
    if (tid < 24) s_perm[tid] = c_perm_packed[tid];
    __syncthreads();

    // ---- phase 2: 4 one-positions of row w (order irrelevant: min over perms) ----
    int cnt = 0;
    #pragma unroll
    for (int i = 0; i < 6; i++) {
        int c = i * 32 + lane;
        int v = (c < NC) ? s_lab[w * NC + c] : 0;
        bool f = (v == 1);
        unsigned m = __ballot_sync(0xffffffffu, f);
        if (f) {
            int pos = cnt + __popc(m & ((1u << lane) - 1u));
            if (pos < 4) s_idx[w][pos] = c;
        }
        cnt += __popc(m);
    }
    __syncwarp();

    // ---- phase 3: 16 lanes compute the 4x4 cost matrix ----
    if (lane < 16) {
        int i = lane >> 2, j = lane & 3;
        float a = s_doa[w][i];
        float b = ((float)s_idx[w][j] - 90.0f) * (PI_F / 180.0f);
        float x = a - b + PI_F;
        float m = x - TWOPI_F * floorf(x * INV_TWOPI_F);  // mod(x, 2pi) in [0,2pi)
        float d = m - PI_F;
        s_cost[w][lane] = d * d;
    }
    __syncwarp();

    // ---- phase 4: 24 lanes each evaluate one permutation; warp-min ----
    float t = 3.402823466e+38f;
    if (lane < 24) {
        unsigned p = s_perm[lane];
        t = s_cost[w][      (p        & 0xffu)]
          + s_cost[w][ 4 + ((p >>  8) & 0xffu)]
          + s_cost[w][ 8 + ((p >> 16) & 0xffu)]
          + s_cost[w][12 + ( p >> 24        )];
    }
    #pragma unroll
    for (int off = 16; off; off >>= 1)
        t = fminf(t, __shfl_xor_sync(0xffffffffu, t, off));
    if (lane == 0) s_part[w] = sqrtf(t * 0.25f);
    __syncthreads();

    // ---- phase 5: block reduce + last-block epilogue ----
    if (tid == 0) {
        float x = 0.0f;
        #pragma unroll
        for (int r = 0; r < ROWS_PER_BLOCK; r++) x += s_part[r];
        atomicAdd(&g_acc, (double)x);
        __threadfence();
        unsigned prev = atomicAdd(&g_done, 1u);
        if (prev == NBLOCKS - 1) {
            __threadfence();
            double total = *((volatile double*)&g_acc);
            out[0] = (float)(total / (double)BATCH);
            g_acc  = 0.0;   // deterministic state for the next graph replay
            g_done = 0u;
        }
    }
}

extern "C" void kernel_launch(void* const* d_in, const int* in_sizes, int n_in,
                              void* d_out, int out_size) {
    const float* logits = (const float*)d_in[0];
    const int*   labels = (const int*)d_in[1];
    float* out = (float*)d_out;

    rmspe_main<<<NBLOCKS, THREADS>>>(logits, labels, out);
}